// round 17
// baseline (speedup 1.0000x reference)
#include <cuda_runtime.h>
#include <cuda_fp16.h>
#include <math.h>
#include <stdint.h>

// Problem constants
#define Bb 8
#define Nn 1024
#define Cc 768
#define Hh 12
#define Dd 64
#define Mtot (Bb*Nn)      // 8192
#define N1 (3*Cc)         // 2304
#define NQK 1536          // q,k columns only

// Scratch (device globals).
__device__ int8_t g_q4s[Bb*Hh*Nn*Dd];   // q4 codes of q8 q (s8 MMA operand)
__device__ int8_t g_k4s[Bb*Hh*Nn*Dd];   // q4 codes of q8 k
__device__ __half g_aoh[Bb*Hh*Nn*Dd];   // attention out, q8
__device__ __half g_xqh[Mtot*Cc];       // pre-quantized inputs
__device__ __half g_wqh[N1*Cc];
__device__ __half g_wph[Cc*Cc];
__device__ int    g_flag[Bb*Nn];        // per (b,n): attention row nonzero?

__device__ __forceinline__ float q8f(float v){ return rintf(v*128.0f)*0.0078125f; }

__device__ __forceinline__ void mma16(float* c, const uint32_t* a, uint32_t b0, uint32_t b1){
    asm volatile("mma.sync.aligned.m16n8k16.row.col.f32.f16.f16.f32 "
        "{%0,%1,%2,%3}, {%4,%5,%6,%7}, {%8,%9}, {%0,%1,%2,%3};\n"
        : "+f"(c[0]),"+f"(c[1]),"+f"(c[2]),"+f"(c[3])
        : "r"(a[0]),"r"(a[1]),"r"(a[2]),"r"(a[3]), "r"(b0),"r"(b1));
}
// s8 x s8 -> s32, m16n8k32
__device__ __forceinline__ void mmai(int* c, const uint32_t* a, uint32_t b0, uint32_t b1){
    asm volatile("mma.sync.aligned.m16n8k32.row.col.s32.s8.s8.s32 "
        "{%0,%1,%2,%3}, {%4,%5,%6,%7}, {%8,%9}, {%0,%1,%2,%3};\n"
        : "+r"(c[0]),"+r"(c[1]),"+r"(c[2]),"+r"(c[3])
        : "r"(a[0]),"r"(a[1]),"r"(a[2]),"r"(a[3]), "r"(b0),"r"(b1));
}
__device__ __forceinline__ uint32_t ldh2(const __half* p){ return *(const uint32_t*)p; }

__device__ __forceinline__ uint32_t smem_u32(const void* p){
    uint32_t a;
    asm("{ .reg .u64 t; cvta.to.shared.u64 t, %1; cvt.u32.u64 %0, t; }" : "=r"(a) : "l"(p));
    return a;
}
#define LDSM4(r, addr) \
    asm volatile("ldmatrix.sync.aligned.m8n8.x4.shared.b16 {%0,%1,%2,%3}, [%4];" \
        : "=r"((r)[0]),"=r"((r)[1]),"=r"((r)[2]),"=r"((r)[3]) : "r"(addr))

__device__ __forceinline__ void cp16g(void* smem_dst, const void* gsrc){
    uint32_t s = (uint32_t)__cvta_generic_to_shared(smem_dst);
    asm volatile("cp.async.cg.shared.global [%0], [%1], 16;\n" :: "r"(s), "l"(gsrc));
}
#define CP_COMMIT() asm volatile("cp.async.commit_group;\n"::)
#define CP_WAIT1()  asm volatile("cp.async.wait_group 1;\n"::)
#define CP_WAIT0()  asm volatile("cp.async.wait_group 0;\n"::)

// ---------------------------------------------------------------------------
// Pre-quantize x, w_qkv, w_proj -> fp16; zero flags; pre-fill out with bias.
// ---------------------------------------------------------------------------
#define NX4 (Mtot*Cc/4)
#define NW4 (N1*Cc/4)
#define NP4 (Cc*Cc/4)
#define NQ4 (NX4+NW4+NP4)
#define NO4 (Mtot*Cc/4)
#define PREP_ITEMS (NQ4+NO4)
__global__ __launch_bounds__(256) void quant_prep(
        const float* __restrict__ X, const float* __restrict__ Wq,
        const float* __restrict__ Wp, const float* __restrict__ bias,
        float* __restrict__ out)
{
    int i = blockIdx.x*256 + threadIdx.x;
    if(i < Bb*Nn) g_flag[i] = 0;
    if(i < NQ4){
        const float* src; __half* dst;
        if(i < NX4){ src = X; dst = g_xqh; }
        else if(i < NX4+NW4){ src = Wq; dst = g_wqh; i -= NX4; }
        else { src = Wp; dst = g_wph; i -= NX4+NW4; }
        float4 v = ((const float4*)src)[i];
        __half2* d2 = (__half2*)dst;
        d2[2*i]   = __halves2half2(__float2half_rn(q8f(v.x)), __float2half_rn(q8f(v.y)));
        d2[2*i+1] = __halves2half2(__float2half_rn(q8f(v.z)), __float2half_rn(q8f(v.w)));
    } else if(i < PREP_ITEMS){
        int j = i - NQ4;
        int col4 = j % (Cc/4);
        ((float4*)out)[j] = ((const float4*)bias)[col4];
    }
}

// ---------------------------------------------------------------------------
// GEMMs: R8 structure — 128x128 tile, K-chunk 32, 3-stage cp.async ring,
// ldmatrix fragments.  PROJ=0: q,k only (N=1536), epilogue stores s8 q4 code.
// PROJ=1: proj; zero-flag tiles exit (out pre-filled with bias).
// ---------------------------------------------------------------------------
#define HS 40
#define STG (128*HS)
#define STGB (STG*2)
#define GEMM3_SMEM (6*STG*2)  // 61440 B

template<int PROJ>
__global__ __launch_bounds__(256,2) void gemm_h3(
        const float* __restrict__ bias, float* __restrict__ out)
{
    extern __shared__ __half hsm[];
    __half* Ah = hsm;            // [3][STG]
    __half* Bh = hsm + 3*STG;    // [3][STG]
    uint32_t sbA = smem_u32(Ah), sbB = smem_u32(Bh);

    int m0 = blockIdx.y*128, n0 = blockIdx.x*128;
    int tid = threadIdx.x, lane = tid&31, warp = tid>>5;
    int g = lane>>2, tg = lane&3;
    int wm = warp>>2, wn = warp&3;
    int bidx  = m0>>10;
    int nbase = m0&1023;
    const __half* Abase = g_aoh + (size_t)bidx*(Hh*Nn*Dd);
    const __half* Wsrc  = PROJ ? g_wph : g_wqh;

    if(PROJ){
        __shared__ int tflag;
        if(tid==0) tflag = 0;
        __syncthreads();
        if(tid < 128 && g_flag[bidx*Nn + nbase + tid]) tflag = 1;
        __syncthreads();
        if(!tflag) return;           // out already holds bias rows
    }

    float acc[4][4][4];
    #pragma unroll
    for(int a=0;a<4;a++)
        #pragma unroll
        for(int b=0;b<4;b++)
            #pragma unroll
            for(int c=0;c<4;c++) acc[a][b][c]=0.f;

    uint32_t aoff[4], boff[2];
    #pragma unroll
    for(int mt=0;mt<4;mt++)
        aoff[mt] = (uint32_t)((wm*64 + mt*16 + (lane&15))*HS + (lane>>4)*8);
    #pragma unroll
    for(int p=0;p<2;p++)
        boff[p] = (uint32_t)((wn*32 + p*16 + (lane>>4)*8 + (lane&7))*HS
                             + ((lane>>3)&1)*8);

    int srow = tid>>2, sc8 = tid&3;

    auto stage = [&](int st){
        int slot = st - (st/3)*3;
        int c  = st*32 + sc8*8;
        #pragma unroll
        for(int r=0;r<2;r++){
            const __half* asrc;
            if(PROJ){
                int h = c>>6, dd = c&63;
                asrc = Abase + ((size_t)h*Nn + nbase + srow + r*64)*Dd + dd;
            } else {
                asrc = g_xqh + (size_t)(m0 + srow + r*64)*Cc + c;
            }
            cp16g(&Ah[slot*STG + (srow+r*64)*HS + sc8*8], asrc);
            cp16g(&Bh[slot*STG + (srow+r*64)*HS + sc8*8],
                  Wsrc + (size_t)(n0 + srow + r*64)*Cc + c);
        }
    };

    stage(0); CP_COMMIT();
    stage(1); CP_COMMIT();

    for(int s=0;s<24;s++){
        CP_WAIT1();
        __syncthreads();
        if(s+2<24) stage(s+2);
        CP_COMMIT();
        int slot = s - (s/3)*3;
        uint32_t baseA = sbA + slot*STGB;
        uint32_t baseB = sbB + slot*STGB;
        #pragma unroll
        for(int ks=0;ks<2;ks++){
            uint32_t af[4][4], bf[2][4];
            #pragma unroll
            for(int mt=0;mt<4;mt++)
                LDSM4(af[mt], baseA + (aoff[mt] + ks*16)*2);
            #pragma unroll
            for(int p=0;p<2;p++)
                LDSM4(bf[p], baseB + (boff[p] + ks*16)*2);
            #pragma unroll
            for(int mt=0;mt<4;mt++)
                #pragma unroll
                for(int p=0;p<2;p++){
                    mma16(acc[mt][2*p  ], af[mt], bf[p][0], bf[p][1]);
                    mma16(acc[mt][2*p+1], af[mt], bf[p][2], bf[p][3]);
                }
        }
    }

    // epilogue
    #pragma unroll
    for(int mt=0;mt<4;mt++)
        #pragma unroll
        for(int nt=0;nt<4;nt++)
            #pragma unroll
            for(int i=0;i<4;i++){
                int mrow = m0 + wm*64 + mt*16 + g + ((i>=2)?8:0);
                int col  = n0 + wn*32 + nt*8 + 2*tg + (i&1);
                if(PROJ){
                    out[(size_t)mrow*Cc + col] = acc[mt][nt][i] + bias[col];
                } else {
                    int bb = mrow>>10, nrow = mrow&1023;
                    int t = col/Cc, rem = col - t*Cc;
                    int h = rem>>6, dd = rem&63;
                    // q4 code of q8 value (exact small integer)
                    int code = (int)rintf(q8f(acc[mt][nt][i])*8.0f);
                    size_t idx = (((size_t)(bb*Hh)+h)*Nn + nrow)*Dd + dd;
                    if(t==0) g_q4s[idx] = (int8_t)code;
                    else     g_k4s[idx] = (int8_t)code;
                }
            }
}

// ---------------------------------------------------------------------------
// Attention v9: s8 IMMA gate (exact integer dots), exp-free max-only stats.
// raw q4 dot = i/64; winner needs i_gap > 2352 (= floor(64*8*ln99)).
// ---------------------------------------------------------------------------
#define ASB 80                 // smem row stride (bytes) for s8 tiles
#define GAP_ITHR 2352          // integer threshold (exact)

__global__ __launch_bounds__(512) void attn_v9()
{
    __shared__ __align__(16) int8_t qm[128*ASB];
    __shared__ __align__(16) int8_t kt[2][64*ASB];
    __shared__ int red[2*128*2];

    int bh = blockIdx.y;
    int bb = bh/Hh, hh = bh - bb*Hh;
    int q0 = blockIdx.x*128;
    const int8_t* Q4 = g_q4s + (size_t)bh*(Nn*Dd);
    const int8_t* K4 = g_k4s + (size_t)bh*(Nn*Dd);
    __half*       Oph= g_aoh + (size_t)bh*(Nn*Dd);

    int tid = threadIdx.x, lane = tid&31, warp = tid>>5;
    int g = lane>>2, tg = lane&3;
    int wm = warp>>1, wn = warp&1;
    int r0 = wm*16 + g;

    // prologue: K tile 0 (rows 64B, tid<256) + q tile (tid covers 512 chunks)
    if(tid < 256){
        int row = tid>>2, c16 = tid&3;
        cp16g(&kt[0][row*ASB + c16*16], K4 + (size_t)row*Dd + c16*16);
    }
    { int row = tid>>2, c16 = tid&3;
      cp16g(&qm[row*ASB + c16*16], Q4 + (size_t)(q0+row)*Dd + c16*16); }
    CP_COMMIT();
    CP_WAIT0();
    __syncthreads();

    // hoist A fragments (2 k32-steps)
    uint32_t am[2][4];
    #pragma unroll
    for(int ks=0;ks<2;ks++){
        const int8_t* pr0 = &qm[r0*ASB + ks*32 + tg*4];
        const int8_t* pr8 = &qm[(r0+8)*ASB + ks*32 + tg*4];
        am[ks][0] = *(const uint32_t*)pr0;
        am[ks][1] = *(const uint32_t*)pr8;
        am[ks][2] = *(const uint32_t*)(pr0 + 16);
        am[ks][3] = *(const uint32_t*)(pr8 + 16);
    }

    int mx0 = INT_MIN/2, mx1 = INT_MIN/2;
    for(int t=0;t<16;t++){
        if(t<15){
            if(tid < 256){
                int row = tid>>2, c16 = tid&3;
                cp16g(&kt[(t+1)&1][row*ASB + c16*16],
                      K4 + (size_t)((t+1)*64+row)*Dd + c16*16);
            }
            CP_COMMIT();
            CP_WAIT1();
        } else CP_WAIT0();
        __syncthreads();
        const int8_t* kb = kt[t&1];

        int accI[4][4];
        #pragma unroll
        for(int nt=0;nt<4;nt++)
            #pragma unroll
            for(int j=0;j<4;j++) accI[nt][j]=0;
        #pragma unroll
        for(int ks=0;ks<2;ks++){
            #pragma unroll
            for(int nt=0;nt<4;nt++){
                const int8_t* pk = &kb[(wn*32 + nt*8 + g)*ASB + ks*32 + tg*4];
                uint32_t b0 = *(const uint32_t*)pk;
                uint32_t b1 = *(const uint32_t*)(pk + 16);
                mmai(accI[nt], am[ks], b0, b1);
            }
        }

        // tree-max of 8 values per row
        {
            int a  = max(max(accI[0][0],accI[1][0]), max(accI[2][0],accI[3][0]));
            int b2 = max(max(accI[0][1],accI[1][1]), max(accI[2][1],accI[3][1]));
            mx0 = max(mx0, max(a,b2));
            a  = max(max(accI[0][2],accI[1][2]), max(accI[2][2],accI[3][2]));
            b2 = max(max(accI[0][3],accI[1][3]), max(accI[2][3],accI[3][3]));
            mx1 = max(mx1, max(a,b2));
        }
        __syncthreads();
    }

    // cross-lane (max, sec_est)
    int s0e = INT_MIN/2, s1e = INT_MIN/2;
    #pragma unroll
    for(int off=1; off<4; off<<=1){
        int om=__shfl_xor_sync(0xffffffffu,mx0,off);
        int os=__shfl_xor_sync(0xffffffffu,s0e,off);
        s0e = max(max(s0e, os), min(mx0, om));
        mx0 = max(mx0, om);
        om=__shfl_xor_sync(0xffffffffu,mx1,off);
        os=__shfl_xor_sync(0xffffffffu,s1e,off);
        s1e = max(max(s1e, os), min(mx1, om));
        mx1 = max(mx1, om);
    }
    if(tg==0){
        int b0=(wn*128 + r0)*2;
        red[b0]=mx0; red[b0+1]=s0e;
        int b1=(wn*128 + r0+8)*2;
        red[b1]=mx1; red[b1+1]=s1e;
    }
    __syncthreads();

    for(int rr=warp; rr<128; rr+=16){
        int ma=red[rr*2],       sa=red[rr*2+1];
        int mb=red[(128+rr)*2], sb=red[(128+rr)*2+1];
        int m  = max(ma, mb);
        int sc = max(max(sa, sb), min(ma, mb));
        int grow = q0 + rr;
        __half* orow = Oph + (size_t)grow*Dd;

        if(m - sc > GAP_ITHR){
            // RARE exact fallback: recompute row msb int dots -> argmax + s
            int qvi[64];
            #pragma unroll
            for(int d=0; d<64; d++) qvi[d] = (int)qm[rr*ASB + d];
            int ifm = INT_MIN/2, ix = 0;
            for(int kk=0; kk<32; kk++){
                int key = lane + kk*32;
                const int8_t* kr = K4 + (size_t)key*Dd;
                int idot = 0;
                #pragma unroll
                for(int d=0; d<64; d+=4){
                    char4 c4 = *(const char4*)(kr + d);
                    idot += qvi[d]*c4.x + qvi[d+1]*c4.y
                          + qvi[d+2]*c4.z + qvi[d+3]*c4.w;
                }
                if(idot > ifm){ ifm = idot; ix = key; }
            }
            #pragma unroll
            for(int off=16; off; off>>=1){
                int om = __shfl_xor_sync(0xffffffffu, ifm, off);
                int oi = __shfl_xor_sync(0xffffffffu, ix, off);
                if(om > ifm){ ifm = om; ix = oi; }
            }
            float ssum = 0.f;
            for(int kk=0; kk<32; kk++){
                int key = lane + kk*32;
                const int8_t* kr = K4 + (size_t)key*Dd;
                int idot = 0;
                #pragma unroll
                for(int d=0; d<64; d+=4){
                    char4 c4 = *(const char4*)(kr + d);
                    idot += qvi[d]*c4.x + qvi[d+1]*c4.y
                          + qvi[d+2]*c4.z + qvi[d+3]*c4.w;
                }
                ssum += __expf((float)(idot - ifm)*0.001953125f);  // /512
            }
            #pragma unroll
            for(int off=16; off; off>>=1)
                ssum += __shfl_xor_sync(0xffffffffu, ssum, off);

            if(ssum*0.99f < 1.0f){
                // Winner: recompute q8 q/k/v rows from x @ w_qkv (exact).
                const __half* xq = g_xqh + ((size_t)bb*Nn + grow)*Cc;
                const __half* xk = g_xqh + ((size_t)bb*Nn + ix)*Cc;
                float qd[2], kd[2], vd[2];
                #pragma unroll
                for(int j=0;j<2;j++){
                    int d = 2*lane + j;
                    const __half* wq = g_wqh + (size_t)(hh*Dd + d)*Cc;
                    const __half* wk = g_wqh + (size_t)(Cc + hh*Dd + d)*Cc;
                    const __half* wv = g_wqh + (size_t)(2*Cc + hh*Dd + d)*Cc;
                    float aq=0.f, ak=0.f, av=0.f;
                    for(int c=0;c<Cc;c+=2){
                        float2 x1 = __half22float2(*(const __half2*)(xq + c));
                        float2 x2 = __half22float2(*(const __half2*)(xk + c));
                        float2 w1 = __half22float2(*(const __half2*)(wq + c));
                        float2 w2 = __half22float2(*(const __half2*)(wk + c));
                        float2 w3 = __half22float2(*(const __half2*)(wv + c));
                        aq += x1.x*w1.x + x1.y*w1.y;
                        ak += x2.x*w2.x + x2.y*w2.y;
                        av += x2.x*w3.x + x2.y*w3.y;
                    }
                    qd[j]=q8f(aq); kd[j]=q8f(ak); vd[j]=q8f(av);
                }
                float part = qd[0]*kd[0] + qd[1]*kd[1];
                #pragma unroll
                for(int off=16; off; off>>=1)
                    part += __shfl_xor_sync(0xffffffffu, part, off);
                float L  = part*0.125f;
                float mm = fmaxf(L, 0.f);
                float eL = __expf(L-mm);
                float pq = q8f(eL / (eL + 1023.0f*__expf(-mm)));
                orow[2*lane]   = __float2half_rn(q8f(pq*vd[0]));
                orow[2*lane+1] = __float2half_rn(q8f(pq*vd[1]));
                if(lane==0) g_flag[bb*Nn + grow] = 1;
            } else {
                *(__half2*)(orow + 2*lane) = __halves2half2(__float2half_rn(0.f), __float2half_rn(0.f));
            }
        } else {
            *(__half2*)(orow + 2*lane) = __halves2half2(__float2half_rn(0.f), __float2half_rn(0.f));
        }
    }
}

// ---------------------------------------------------------------------------
extern "C" void kernel_launch(void* const* d_in, const int* in_sizes, int n_in,
                              void* d_out, int out_size)
{
    const float* x      = (const float*)d_in[0];
    const float* w_qkv  = (const float*)d_in[1];
    const float* w_proj = (const float*)d_in[2];
    const float* b_proj = (const float*)d_in[3];
    float* out = (float*)d_out;

    cudaFuncSetAttribute(gemm_h3<0>, cudaFuncAttributeMaxDynamicSharedMemorySize, GEMM3_SMEM);
    cudaFuncSetAttribute(gemm_h3<1>, cudaFuncAttributeMaxDynamicSharedMemorySize, GEMM3_SMEM);

    quant_prep<<<(PREP_ITEMS+255)/256, 256>>>(x, w_qkv, w_proj, b_proj, out);
    gemm_h3<0><<<dim3(NQK/128, Mtot/128), 256, GEMM3_SMEM>>>(nullptr, nullptr);
    attn_v9<<<dim3(Nn/128, Bb*Hh), 512>>>();
    gemm_h3<1><<<dim3(Cc/128, Mtot/128), 256, GEMM3_SMEM>>>(b_proj, out);
}